// round 2
// baseline (speedup 1.0000x reference)
#include <cuda_runtime.h>
#include <cuda_bf16.h>
#include <cstdint>

// Problem constants
#define BB   4
#define CIN  256
#define COUT 256
#define HH   64
#define WW   64
#define KK9  9
#define KTOT (CIN*KK9)   // 2304

// ---------------- device scratch (no allocations allowed) ----------------
__device__ float g_wT[KTOT * COUT];        // [k][o], k = c*9 + tap      (2.36 MB)
__device__ float g_wofft[KTOT * 32];       // [k][oc] oc<18 off,18..26 mask, pad 0
__device__ float g_offmask[BB*HH*WW*28];   // [b,h,w][28]: 0..17 dy/dx pairs, 18..26 sigmoid(mask)

// ---------------- prep: weight transposes ----------------
__global__ void prep_kernel(const float* __restrict__ w,
                            const float* __restrict__ off_w,
                            const float* __restrict__ mask_w) {
    int idx = blockIdx.x * blockDim.x + threadIdx.x;
    if (idx < KTOT * COUT) {
        int o = idx & 255;
        int k = idx >> 8;
        g_wT[idx] = __ldg(&w[(size_t)o * KTOT + k]);     // write coalesced
    }
    if (idx < KTOT * 32) {
        int oc = idx & 31;
        int k  = idx >> 5;
        float v = 0.f;
        if (oc < 18)      v = __ldg(&off_w [(size_t)oc * KTOT + k]);
        else if (oc < 27) v = __ldg(&mask_w[(size_t)(oc - 18) * KTOT + k]);
        g_wofft[idx] = v;
    }
}

// ---------------- kernel 1: offset/mask conv (27ch 3x3, Cin=256) ----------------
// one block per (b, h) row; 256 threads; M=64 pixels, N=28(pad), K=2304
#define CC1 16
__global__ __launch_bounds__(256, 2)
void k_offmask(const float* __restrict__ x,
               const float* __restrict__ off_b,
               const float* __restrict__ mask_b) {
    __shared__ float xs[CC1][3][66];      // [c][row][col], col = px+1, px in [-1,64]
    __shared__ float ws[CC1 * 9 * 32];    // [(c*9+t)*32 + oc]

    int bh = blockIdx.x;
    int b  = bh >> 6;
    int h  = bh & 63;
    int tid = threadIdx.x;
    int pp = tid & 31;       // pixels pp and pp+32
    int og = tid >> 5;       // output-channel group: oc = og*4 + j

    const float* xb = x + (size_t)b * CIN * HH * WW;
    float acc[2][4] = {};

    for (int c0 = 0; c0 < CIN; c0 += CC1) {
        // stage x rows [h-1, h, h+1], cols [-1..64]
        for (int e = tid; e < CC1 * 3 * 66; e += 256) {
            int c   = e / 198;
            int r   = e % 198;
            int row = r / 66;
            int col = r % 66;
            int y  = h - 1 + row;
            int xp = col - 1;
            float v = 0.f;
            if ((unsigned)y < 64u && (unsigned)xp < 64u)
                v = xb[(size_t)(c0 + c) * 4096 + y * 64 + xp];
            xs[c][row][col] = v;
        }
        // stage weights (contiguous slab)
        const float* src = g_wofft + (size_t)c0 * 9 * 32;
        for (int e = tid; e < CC1 * 288; e += 256) ws[e] = src[e];
        __syncthreads();

        for (int c = 0; c < CC1; ++c) {
            #pragma unroll
            for (int t = 0; t < 9; ++t) {
                int ky = t / 3, kx = t % 3;
                float xv0 = xs[c][ky][pp + kx];
                float xv1 = xs[c][ky][pp + 32 + kx];
                const float* wr = &ws[(c * 9 + t) * 32 + og * 4];
                #pragma unroll
                for (int j = 0; j < 4; ++j) {
                    float wv = wr[j];
                    acc[0][j] = fmaf(xv0, wv, acc[0][j]);
                    acc[1][j] = fmaf(xv1, wv, acc[1][j]);
                }
            }
        }
        __syncthreads();
    }

    #pragma unroll
    for (int half = 0; half < 2; ++half) {
        int pix = pp + half * 32;
        float* dst = g_offmask + ((size_t)bh * 64 + pix) * 28;
        #pragma unroll
        for (int j = 0; j < 4; ++j) {
            int oc = og * 4 + j;
            if (oc < 18) {
                dst[oc] = acc[half][j] + __ldg(&off_b[oc]);
            } else if (oc < 27) {
                float z = acc[half][j] + __ldg(&mask_b[oc - 18]);
                dst[oc] = 1.f / (1.f + __expf(-z));
            }
        }
    }
}

// ---------------- kernel 2: deformable sample + main GEMM ----------------
// one block per (b,h) row: BM=64 pixels x BN=256 outputs, K=2304 in KC=18 slices
#define KC 18
__global__ __launch_bounds__(256, 2)
void k_main(const float* __restrict__ x,
            const float* __restrict__ bias,
            float* __restrict__ out) {
    __shared__ float As[KC][64];        // sampled activations [k_local][pixel]
    __shared__ float Bs[KC][256];       // weights [k_local][o]
    __shared__ float offs[64 * 29];     // per-pixel 28 vals, padded row 29 (bank-conflict free)

    int bh = blockIdx.x;
    int b  = bh >> 6;
    int h  = bh & 63;
    int tid = threadIdx.x;

    // compute mapping: 16x16 thread grid, 4 pixels x 16 outputs each
    int tx = tid & 15, ty = tid >> 4;
    int o0 = tx * 16, p0 = ty * 4;
    // sampling mapping: lanes = pixels (coalesced gathers)
    int spix = tid & 63, s = tid >> 6;

    // stage offsets/mask for this row
    {
        const float* src = g_offmask + (size_t)bh * 64 * 28;
        for (int e = tid; e < 64 * 28; e += 256) {
            int pix = e / 28, c = e % 28;
            offs[pix * 29 + c] = src[e];
        }
    }
    __syncthreads();

    const float* xb = x + (size_t)b * CIN * 4096;
    float acc[4][16] = {};

    for (int cc = 0; cc < KTOT / KC; ++cc) {     // 128 chunks, 2 channels each
        int k0 = cc * KC;
        // --- stage Bs (coalesced) ---
        const float* wsrc = g_wT + (size_t)k0 * 256;
        #pragma unroll
        for (int i = 0; i < KC; ++i) Bs[i][tid] = wsrc[i * 256 + tid];

        // --- stage As via deformable bilinear sampling ---
        int c0 = cc * 2;
        #pragma unroll
        for (int i = 0; i < 5; ++i) {
            int kidx = s + 4 * i;                 // 0..17 = c_local*9 + tap
            if (kidx < KC) {
                int c = kidx / 9;
                int t = kidx - c * 9;
                int ky = t / 3, kx = t - ky * 3;
                float dy = offs[spix * 29 + 2 * t];
                float dx = offs[spix * 29 + 2 * t + 1];
                float m  = offs[spix * 29 + 18 + t];
                float py = (float)(h - 1 + ky) + dy;
                float px = (float)(spix - 1 + kx) + dx;
                float y0f = floorf(py), x0f = floorf(px);
                int iy = (int)y0f, ix = (int)x0f;
                float fy = py - y0f, fx = px - x0f;
                const float* xc = xb + (size_t)(c0 + c) * 4096;
                bool y0v = (unsigned)iy       < 64u;
                bool y1v = (unsigned)(iy + 1) < 64u;
                bool x0v = (unsigned)ix       < 64u;
                bool x1v = (unsigned)(ix + 1) < 64u;
                float v00 = (y0v && x0v) ? xc[iy * 64 + ix]           : 0.f;
                float v01 = (y0v && x1v) ? xc[iy * 64 + ix + 1]       : 0.f;
                float v10 = (y1v && x0v) ? xc[(iy + 1) * 64 + ix]     : 0.f;
                float v11 = (y1v && x1v) ? xc[(iy + 1) * 64 + ix + 1] : 0.f;
                float a0 = fmaf(fx, v01 - v00, v00);
                float a1 = fmaf(fx, v11 - v10, v10);
                float v  = fmaf(fy, a1 - a0, a0);
                As[kidx][spix] = v * m;
            }
        }
        __syncthreads();

        // --- compute: 64 FFMA per k-step per thread ---
        #pragma unroll
        for (int kk = 0; kk < KC; ++kk) {
            float a0 = As[kk][p0 + 0];
            float a1 = As[kk][p0 + 1];
            float a2 = As[kk][p0 + 2];
            float a3 = As[kk][p0 + 3];
            #pragma unroll
            for (int j = 0; j < 16; ++j) {
                float bv = Bs[kk][o0 + j];
                acc[0][j] = fmaf(a0, bv, acc[0][j]);
                acc[1][j] = fmaf(a1, bv, acc[1][j]);
                acc[2][j] = fmaf(a2, bv, acc[2][j]);
                acc[3][j] = fmaf(a3, bv, acc[3][j]);
            }
        }
        __syncthreads();
    }

    // epilogue: out[b][o][h][w], vectorized over w
    #pragma unroll
    for (int j = 0; j < 16; ++j) {
        int o = o0 + j;
        float bv = __ldg(&bias[o]);
        float4 r;
        r.x = acc[0][j] + bv;
        r.y = acc[1][j] + bv;
        r.z = acc[2][j] + bv;
        r.w = acc[3][j] + bv;
        *(float4*)&out[(((size_t)b * COUT + o) * HH + h) * WW + p0] = r;
    }
}

// ---------------- launch ----------------
extern "C" void kernel_launch(void* const* d_in, const int* in_sizes, int n_in,
                              void* d_out, int out_size) {
    const float* x      = (const float*)d_in[0];  // (4,256,64,64)
    const float* weight = (const float*)d_in[1];  // (256,256,3,3)
    const float* bias   = (const float*)d_in[2];  // (256,)
    const float* off_w  = (const float*)d_in[3];  // (18,256,3,3)
    const float* off_b  = (const float*)d_in[4];  // (18,)
    const float* mask_w = (const float*)d_in[5];  // (9,256,3,3)
    const float* mask_b = (const float*)d_in[6];  // (9,)
    float* out = (float*)d_out;                   // (4,256,64,64)

    prep_kernel<<<(KTOT * COUT + 255) / 256, 256>>>(weight, off_w, mask_w);
    k_offmask<<<BB * HH, 256>>>(x, off_b, mask_b);
    k_main<<<BB * HH, 256>>>(x, bias, out);
}

// round 5
// speedup vs baseline: 2.1913x; 2.1913x over previous
#include <cuda_runtime.h>
#include <cuda_bf16.h>
#include <cstdint>

// Problem constants
#define BB   4
#define CIN  256
#define COUT 256
#define HH   64
#define WW   64
#define KK9  9
#define KTOT (CIN*KK9)   // 2304

// ---------------- device scratch (no allocations allowed) ----------------
__device__ float g_wT[KTOT * COUT];        // [k][o], k = c*9 + tap      (2.36 MB)
__device__ float g_wofft[KTOT * 32];       // [k][oc] oc<18 off,18..26 mask, pad 0
__device__ float g_offmask[BB*HH*WW*28];   // [b,h,w][28]: 0..17 dy/dx pairs, 18..26 sigmoid(mask)

// ---------------- prep: weight transposes ----------------
__global__ void prep_kernel(const float* __restrict__ w,
                            const float* __restrict__ off_w,
                            const float* __restrict__ mask_w) {
    int idx = blockIdx.x * blockDim.x + threadIdx.x;
    if (idx < KTOT * COUT) {
        int o = idx & 255;
        int k = idx >> 8;
        g_wT[idx] = __ldg(&w[(size_t)o * KTOT + k]);     // write coalesced
    }
    if (idx < KTOT * 32) {
        int oc = idx & 31;
        int k  = idx >> 5;
        float v = 0.f;
        if (oc < 18)      v = __ldg(&off_w [(size_t)oc * KTOT + k]);
        else if (oc < 27) v = __ldg(&mask_w[(size_t)(oc - 18) * KTOT + k]);
        g_wofft[idx] = v;
    }
}

// ---------------- kernel 1: offset/mask conv (27ch 3x3, Cin=256) ----------------
#define CC1 16
__global__ __launch_bounds__(256, 2)
void k_offmask(const float* __restrict__ x,
               const float* __restrict__ off_b,
               const float* __restrict__ mask_b) {
    __shared__ float xs[CC1][3][66];      // [c][row][col], col = px+1
    __shared__ float ws[CC1 * 9 * 32];    // [(c*9+t)*32 + oc]

    int bh = blockIdx.x;
    int b  = bh >> 6;
    int h  = bh & 63;
    int tid = threadIdx.x;
    int pp = tid & 31;       // pixels pp and pp+32
    int og = tid >> 5;       // output-channel group: oc = og*4 + j

    const float* xb = x + (size_t)b * CIN * HH * WW;
    float acc[2][4] = {};

    for (int c0 = 0; c0 < CIN; c0 += CC1) {
        for (int e = tid; e < CC1 * 3 * 66; e += 256) {
            int c   = e / 198;
            int r   = e % 198;
            int row = r / 66;
            int col = r % 66;
            int y  = h - 1 + row;
            int xp = col - 1;
            float v = 0.f;
            if ((unsigned)y < 64u && (unsigned)xp < 64u)
                v = xb[(size_t)(c0 + c) * 4096 + y * 64 + xp];
            xs[c][row][col] = v;
        }
        const float* src = g_wofft + (size_t)c0 * 9 * 32;
        for (int e = tid; e < CC1 * 288; e += 256) ws[e] = src[e];
        __syncthreads();

        for (int c = 0; c < CC1; ++c) {
            #pragma unroll
            for (int t = 0; t < 9; ++t) {
                int ky = t / 3, kx = t % 3;
                float xv0 = xs[c][ky][pp + kx];
                float xv1 = xs[c][ky][pp + 32 + kx];
                const float* wr = &ws[(c * 9 + t) * 32 + og * 4];
                #pragma unroll
                for (int j = 0; j < 4; ++j) {
                    float wv = wr[j];
                    acc[0][j] = fmaf(xv0, wv, acc[0][j]);
                    acc[1][j] = fmaf(xv1, wv, acc[1][j]);
                }
            }
        }
        __syncthreads();
    }

    #pragma unroll
    for (int half = 0; half < 2; ++half) {
        int pix = pp + half * 32;
        float* dst = g_offmask + ((size_t)bh * 64 + pix) * 28;
        #pragma unroll
        for (int j = 0; j < 4; ++j) {
            int oc = og * 4 + j;
            if (oc < 18) {
                dst[oc] = acc[half][j] + __ldg(&off_b[oc]);
            } else if (oc < 27) {
                float z = acc[half][j] + __ldg(&mask_b[oc - 18]);
                dst[oc] = 1.f / (1.f + __expf(-z));
            }
        }
    }
}

// ---------------- kernel 2: deformable sample + main GEMM ----------------
// one block per (b,h) row: BM=64 pixels x BN=256 outputs, K=2304 in KC=18 slices
// thread tile: 4 pixels x 16 outputs, outputs laid out as 4 float4 groups at
// stride 64 (o = tx*4 + g*64 + j) -> LDS.128 B loads with only 2-way conflicts.
#define KC 18
__global__ __launch_bounds__(256, 2)
void k_main(const float* __restrict__ x,
            const float* __restrict__ bias,
            float* __restrict__ out) {
    __shared__ __align__(16) float As[KC][64];   // sampled activations [k_local][pixel]
    __shared__ __align__(16) float Bs[KC][256];  // weights [k_local][o]
    __shared__ float offs[64 * 29];              // per-pixel 28 vals, padded row 29

    int bh = blockIdx.x;
    int b  = bh >> 6;
    int h  = bh & 63;
    int tid = threadIdx.x;

    // compute mapping: 16x16 thread grid
    int tx = tid & 15, ty = tid >> 4;
    int p0 = ty * 4;                 // 4 pixels
    int ob = tx * 4;                 // output base; groups at ob + g*64
    // sampling mapping: lanes = pixels (coalesced gathers)
    int spix = tid & 63, s = tid >> 6;

    // stage offsets/mask for this row
    {
        const float* src = g_offmask + (size_t)bh * 64 * 28;
        for (int e = tid; e < 64 * 28; e += 256) {
            int pix = e / 28, c = e % 28;
            offs[pix * 29 + c] = src[e];
        }
    }
    __syncthreads();

    const float* xb = x + (size_t)b * CIN * 4096;
    float acc[4][16] = {};   // [pixel][g*4+j]

    for (int cc = 0; cc < KTOT / KC; ++cc) {     // 128 chunks, 2 channels each
        int k0 = cc * KC;
        // --- stage Bs (coalesced float4: 18*256 floats = 1152 float4) ---
        {
            const float4* wsrc = (const float4*)(g_wT + (size_t)k0 * 256);
            float4* bdst = (float4*)&Bs[0][0];
            #pragma unroll
            for (int i = 0; i < 5; ++i) {
                int e = tid + 256 * i;
                if (e < KC * 64) bdst[e] = wsrc[e];
            }
        }

        // --- stage As via deformable bilinear sampling ---
        int c0 = cc * 2;
        #pragma unroll
        for (int i = 0; i < 5; ++i) {
            int kidx = s + 4 * i;                 // 0..17 = c_local*9 + tap
            if (kidx < KC) {
                int c = kidx / 9;
                int t = kidx - c * 9;
                int ky = t / 3, kx = t - ky * 3;
                float dy = offs[spix * 29 + 2 * t];
                float dx = offs[spix * 29 + 2 * t + 1];
                float m  = offs[spix * 29 + 18 + t];
                float py = (float)(h - 1 + ky) + dy;
                float px = (float)(spix - 1 + kx) + dx;
                float y0f = floorf(py), x0f = floorf(px);
                int iy = (int)y0f, ix = (int)x0f;
                float fy = py - y0f, fx = px - x0f;
                const float* xc = xb + (size_t)(c0 + c) * 4096;
                bool y0v = (unsigned)iy       < 64u;
                bool y1v = (unsigned)(iy + 1) < 64u;
                bool x0v = (unsigned)ix       < 64u;
                bool x1v = (unsigned)(ix + 1) < 64u;
                float v00 = (y0v && x0v) ? xc[iy * 64 + ix]           : 0.f;
                float v01 = (y0v && x1v) ? xc[iy * 64 + ix + 1]       : 0.f;
                float v10 = (y1v && x0v) ? xc[(iy + 1) * 64 + ix]     : 0.f;
                float v11 = (y1v && x1v) ? xc[(iy + 1) * 64 + ix + 1] : 0.f;
                float a0 = fmaf(fx, v01 - v00, v00);
                float a1 = fmaf(fx, v11 - v10, v10);
                float v  = fmaf(fy, a1 - a0, a0);
                As[kidx][spix] = v * m;
            }
        }
        __syncthreads();

        // --- compute: 64 FFMA per k-step, 5 LDS.128 per k-step ---
        #pragma unroll 3
        for (int kk = 0; kk < KC; ++kk) {
            float4 av  = *(const float4*)&As[kk][p0];
            float4 bv0 = *(const float4*)&Bs[kk][ob];
            float4 bv1 = *(const float4*)&Bs[kk][ob + 64];
            float4 bv2 = *(const float4*)&Bs[kk][ob + 128];
            float4 bv3 = *(const float4*)&Bs[kk][ob + 192];
            const float a4[4] = {av.x, av.y, av.z, av.w};
            const float b16[16] = {bv0.x, bv0.y, bv0.z, bv0.w,
                                   bv1.x, bv1.y, bv1.z, bv1.w,
                                   bv2.x, bv2.y, bv2.z, bv2.w,
                                   bv3.x, bv3.y, bv3.z, bv3.w};
            #pragma unroll
            for (int p = 0; p < 4; ++p) {
                #pragma unroll
                for (int j = 0; j < 16; ++j)
                    acc[p][j] = fmaf(a4[p], b16[j], acc[p][j]);
            }
        }
        __syncthreads();
    }

    // epilogue: out[b][o][h][w], float4 over w
    #pragma unroll
    for (int g = 0; g < 4; ++g) {
        #pragma unroll
        for (int j = 0; j < 4; ++j) {
            int o = ob + g * 64 + j;
            float bv = __ldg(&bias[o]);
            float4 r;
            r.x = acc[0][g * 4 + j] + bv;
            r.y = acc[1][g * 4 + j] + bv;
            r.z = acc[2][g * 4 + j] + bv;
            r.w = acc[3][g * 4 + j] + bv;
            *(float4*)&out[(((size_t)b * COUT + o) * HH + h) * WW + p0] = r;
        }
    }
}

// ---------------- launch ----------------
extern "C" void kernel_launch(void* const* d_in, const int* in_sizes, int n_in,
                              void* d_out, int out_size) {
    const float* x      = (const float*)d_in[0];  // (4,256,64,64)
    const float* weight = (const float*)d_in[1];  // (256,256,3,3)
    const float* bias   = (const float*)d_in[2];  // (256,)
    const float* off_w  = (const float*)d_in[3];  // (18,256,3,3)
    const float* off_b  = (const float*)d_in[4];  // (18,)
    const float* mask_w = (const float*)d_in[5];  // (9,256,3,3)
    const float* mask_b = (const float*)d_in[6];  // (9,)
    float* out = (float*)d_out;                   // (4,256,64,64)

    prep_kernel<<<(KTOT * COUT + 255) / 256, 256>>>(weight, off_w, mask_w);
    k_offmask<<<BB * HH, 256>>>(x, off_b, mask_b);
    k_main<<<BB * HH, 256>>>(x, bias, out);
}

// round 10
// speedup vs baseline: 3.5039x; 1.5990x over previous
#include <cuda_runtime.h>
#include <cuda_bf16.h>
#include <cstdint>

// Problem constants
#define BB   4
#define CIN  256
#define COUT 256
#define KTOT 2304
#define KC   32
#define NCH  72          // KTOT/KC
#define BROW 40          // padded smem row (bf16 elems): 80 B, 16B-aligned, ldmatrix conflict-free

// ---------------- device scratch (no allocations allowed) ----------------
__device__ float g_wofft[KTOT * 32];          // offset/mask conv weights [k][oc]
__device__ float g_offmask[BB*64*64*28];      // [b,h,w][28]
// Main weights, bf16 hi/lo split, padded rows, chunked: [ch][hi/lo][o][BROW]
__device__ __align__(16) __nv_bfloat16 g_wb[NCH * 2 * COUT * BROW];   // ~2.95 MB

// ---------------- PTX helpers (baseline ISA only: sm_80+ features) ----------------
__device__ __forceinline__ uint32_t smem_u32(const void* p) {
    uint32_t a;
    asm("{ .reg .u64 t; cvta.to.shared.u64 t, %1; cvt.u32.u64 %0, t; }" : "=r"(a) : "l"(p));
    return a;
}
__device__ __forceinline__ void cp16(uint32_t s, const void* g) {
    asm volatile("cp.async.cg.shared.global [%0], [%1], 16;" :: "r"(s), "l"(g));
}
#define CP_COMMIT() asm volatile("cp.async.commit_group;" ::: "memory")
#define CP_WAIT1()  asm volatile("cp.async.wait_group 1;" ::: "memory")
#define CP_WAIT0()  asm volatile("cp.async.wait_group 0;" ::: "memory")

__device__ __forceinline__ void ldsm4(uint32_t& r0, uint32_t& r1, uint32_t& r2, uint32_t& r3, uint32_t a) {
    asm volatile("ldmatrix.sync.aligned.m8n8.x4.shared.b16 {%0,%1,%2,%3}, [%4];"
                 : "=r"(r0), "=r"(r1), "=r"(r2), "=r"(r3) : "r"(a));
}
__device__ __forceinline__ void mma16816(float* d,
                                         uint32_t a0, uint32_t a1, uint32_t a2, uint32_t a3,
                                         uint32_t b0, uint32_t b1) {
    asm volatile("mma.sync.aligned.m16n8k16.row.col.f32.bf16.bf16.f32 "
                 "{%0,%1,%2,%3}, {%4,%5,%6,%7}, {%8,%9}, {%0,%1,%2,%3};"
                 : "+f"(d[0]), "+f"(d[1]), "+f"(d[2]), "+f"(d[3])
                 : "r"(a0), "r"(a1), "r"(a2), "r"(a3), "r"(b0), "r"(b1));
}

// SMEM layout (bytes, dynamic)
#define BCHUNK (2 * COUT * BROW * 2)           // 40960 B per chunk image (hi+lo)
#define SM_B    0                               // double buffered: 2 * 40960
#define SM_AH   (2 * BCHUNK)                    // 81920: As hi, 2 * (128*BROW*2 = 10240)
#define SM_AL   (SM_AH + 2 * 10240)             // 102400: As lo, 2 * 10240
#define SM_OFFS (SM_AL + 2 * 10240)             // 122880: float[2*1856]
#define SMEM_TOTAL (SM_OFFS + 2 * 1856 * 4)     // 137728

// ---------------- prep: weight split + conv-weight transpose ----------------
__global__ void prep_kernel(const float* __restrict__ w,
                            const float* __restrict__ off_w,
                            const float* __restrict__ mask_w) {
    int idx = blockIdx.x * blockDim.x + threadIdx.x;
    if (idx < COUT * KTOT) {
        int o = idx / KTOT;
        int k = idx - o * KTOT;          // k = c*9 + tap (matches w layout [o][c][3][3])
        float f = __ldg(&w[idx]);
        __nv_bfloat16 hi = __float2bfloat16(f);
        __nv_bfloat16 lo = __float2bfloat16(f - __bfloat162float(hi));
        int ch = k >> 5;
        int kk = k & 31;
        g_wb[((size_t)(ch * 2 + 0) * COUT + o) * BROW + kk] = hi;
        g_wb[((size_t)(ch * 2 + 1) * COUT + o) * BROW + kk] = lo;
    }
    if (idx < KTOT * 32) {
        int oc = idx & 31;
        int k  = idx >> 5;
        float v = 0.f;
        if (oc < 18)      v = __ldg(&off_w [(size_t)oc * KTOT + k]);
        else if (oc < 27) v = __ldg(&mask_w[(size_t)(oc - 18) * KTOT + k]);
        g_wofft[idx] = v;
    }
}

// ---------------- kernel 1: offset/mask conv (unchanged, FFMA) ----------------
#define CC1 16
__global__ __launch_bounds__(256, 2)
void k_offmask(const float* __restrict__ x,
               const float* __restrict__ off_b,
               const float* __restrict__ mask_b) {
    __shared__ float xs[CC1][3][66];
    __shared__ float ws[CC1 * 9 * 32];

    int bh = blockIdx.x;
    int b  = bh >> 6;
    int h  = bh & 63;
    int tid = threadIdx.x;
    int pp = tid & 31;
    int og = tid >> 5;

    const float* xb = x + (size_t)b * CIN * 4096;
    float acc[2][4] = {};

    for (int c0 = 0; c0 < CIN; c0 += CC1) {
        for (int e = tid; e < CC1 * 3 * 66; e += 256) {
            int c   = e / 198;
            int r   = e % 198;
            int row = r / 66;
            int col = r % 66;
            int y  = h - 1 + row;
            int xp = col - 1;
            float v = 0.f;
            if ((unsigned)y < 64u && (unsigned)xp < 64u)
                v = xb[(size_t)(c0 + c) * 4096 + y * 64 + xp];
            xs[c][row][col] = v;
        }
        const float* src = g_wofft + (size_t)c0 * 9 * 32;
        for (int e = tid; e < CC1 * 288; e += 256) ws[e] = src[e];
        __syncthreads();

        for (int c = 0; c < CC1; ++c) {
            #pragma unroll
            for (int t = 0; t < 9; ++t) {
                int ky = t / 3, kx = t % 3;
                float xv0 = xs[c][ky][pp + kx];
                float xv1 = xs[c][ky][pp + 32 + kx];
                const float* wr = &ws[(c * 9 + t) * 32 + og * 4];
                #pragma unroll
                for (int j = 0; j < 4; ++j) {
                    float wv = wr[j];
                    acc[0][j] = fmaf(xv0, wv, acc[0][j]);
                    acc[1][j] = fmaf(xv1, wv, acc[1][j]);
                }
            }
        }
        __syncthreads();
    }

    #pragma unroll
    for (int half = 0; half < 2; ++half) {
        int pix = pp + half * 32;
        float* dst = g_offmask + ((size_t)bh * 64 + pix) * 28;
        #pragma unroll
        for (int j = 0; j < 4; ++j) {
            int oc = og * 4 + j;
            if (oc < 18) {
                dst[oc] = acc[half][j] + __ldg(&off_b[oc]);
            } else if (oc < 27) {
                float z = acc[half][j] + __ldg(&mask_b[oc - 18]);
                dst[oc] = 1.f / (1.f + __expf(-z));
            }
        }
    }
}

// ---------------- kernel 2: deformable sample + bf16-split HMMA GEMM ----------------
// CTA: 128 px (2 rows) x 256 outs, 512 threads / 16 warps.
// Warp w: mi = w&3 (32-px tile), nb = w>>2 (64-out block). acc fp32 in regs.
// Pipeline: B cp.async for chunk ch+1 queued only AFTER the compute of chunk
// ch-1 (the last reader of buffer (ch+1)&1) has synced.
__global__ __launch_bounds__(512, 1)
void k_main(const float* __restrict__ x,
            const float* __restrict__ bias,
            float* __restrict__ out) {
    extern __shared__ __align__(16) unsigned char smem[];
    uint32_t sbase = smem_u32(smem);
    float* offs = (float*)(smem + SM_OFFS);

    int tid = threadIdx.x;
    int wid = tid >> 5;
    int lane = tid & 31;
    int bh = blockIdx.x;        // 0..127
    int b  = bh >> 5;
    int hp = bh & 31;           // image rows 2hp, 2hp+1

    // stage offsets/masks for both rows: offs[r*1856 + px*29 + c]
    for (int e = tid; e < 2 * 64 * 28; e += 512) {
        int r = e / 1792;
        int rem = e - r * 1792;
        int pix = rem / 28;
        int cc = rem - pix * 28;
        offs[r * 1856 + pix * 29 + cc] =
            g_offmask[(((size_t)(b * 64 + 2 * hp + r)) * 64 + pix) * 28 + cc];
    }
    __syncthreads();

    const float* xb = x + (size_t)b * CIN * 4096;
    int p_img = tid & 127;      // pixel 0..127
    int ks = tid >> 7;          // 0..3
    int r_img = p_img >> 6;
    int w_img = p_img & 63;
    int h_img = 2 * hp + r_img;
    const float* orow = offs + r_img * 1856 + w_img * 29;

    float acc[8][2][4];
    #pragma unroll
    for (int g = 0; g < 8; ++g)
        #pragma unroll
        for (int mt = 0; mt < 2; ++mt)
            #pragma unroll
            for (int j = 0; j < 4; ++j) acc[g][mt][j] = 0.f;

    // prologue: stage B chunk 0 into buffer 0
    {
        const char* src = (const char*)(g_wb);
        uint32_t dstb = sbase + SM_B;
        #pragma unroll
        for (int i = 0; i < 5; ++i)
            cp16(dstb + (tid + 512 * i) * 16, src + (size_t)(tid + 512 * i) * 16);
    }
    CP_COMMIT();

    for (int ch = 0; ch <= NCH; ++ch) {
        // ---- stage A chunk ch into buffer ch&1 (plain smem stores) ----
        if (ch < NCH) {
            int p = ch & 1;
            int k0 = ch * KC;
            uint32_t aoff_h = SM_AH + p * 10240 + (uint32_t)p_img * 80u;
            uint32_t aoff_l = SM_AL + p * 10240 + (uint32_t)p_img * 80u;
            #pragma unroll
            for (int i = 0; i < 4; ++i) {
                int kp = ks + 4 * i;            // pair index 0..15
                uint32_t ph = 0, pl = 0;
                #pragma unroll
                for (int s2 = 0; s2 < 2; ++s2) {
                    int k = k0 + 2 * kp + s2;
                    int c = (int)((unsigned)k / 9u);
                    int t = k - 9 * c;
                    int kyy = t / 3, kxx = t - kyy * 3;
                    float dy = orow[2 * t];
                    float dx = orow[2 * t + 1];
                    float m  = orow[18 + t];
                    float py = (float)(h_img - 1 + kyy) + dy;
                    float px = (float)(w_img - 1 + kxx) + dx;
                    float y0f = floorf(py), x0f = floorf(px);
                    int iy = (int)y0f, ix = (int)x0f;
                    float fy = py - y0f, fx = px - x0f;
                    const float* xc = xb + (size_t)c * 4096;
                    bool y0v = (unsigned)iy       < 64u;
                    bool y1v = (unsigned)(iy + 1) < 64u;
                    bool x0v = (unsigned)ix       < 64u;
                    bool x1v = (unsigned)(ix + 1) < 64u;
                    float v00 = (y0v && x0v) ? xc[iy * 64 + ix]           : 0.f;
                    float v01 = (y0v && x1v) ? xc[iy * 64 + ix + 1]       : 0.f;
                    float v10 = (y1v && x0v) ? xc[(iy + 1) * 64 + ix]     : 0.f;
                    float v11 = (y1v && x1v) ? xc[(iy + 1) * 64 + ix + 1] : 0.f;
                    float a0 = fmaf(fx, v01 - v00, v00);
                    float a1 = fmaf(fx, v11 - v10, v10);
                    float v  = fmaf(fy, a1 - a0, a0) * m;
                    __nv_bfloat16 hi = __float2bfloat16(v);
                    __nv_bfloat16 lo = __float2bfloat16(v - __bfloat162float(hi));
                    ph |= (uint32_t)__bfloat16_as_ushort(hi) << (16 * s2);
                    pl |= (uint32_t)__bfloat16_as_ushort(lo) << (16 * s2);
                }
                *(uint32_t*)(smem + aoff_h + kp * 4) = ph;
                *(uint32_t*)(smem + aoff_l + kp * 4) = pl;
            }
        }

        // ---- compute chunk ch-1 from buffer (ch-1)&1 ----
        if (ch > 0) {
            int cp = (ch - 1) & 1;
            if (ch == NCH) { CP_WAIT0(); } else { CP_WAIT1(); }   // B of chunk ch-1 resident
            __syncthreads();            // A stores of chunk ch-1 visible, B landed for all

            int mi = wid & 3;
            int nb = wid >> 2;
            int px0 = mi * 32;
            uint32_t abase_h = sbase + SM_AH + cp * 10240 + (uint32_t)px0 * 80u;
            uint32_t abase_l = sbase + SM_AL + cp * 10240 + (uint32_t)px0 * 80u;
            uint32_t bbase_h = sbase + SM_B + cp * BCHUNK + (uint32_t)(nb * 64) * 80u;
            uint32_t bbase_l = bbase_h + 20480u;
            int rrow = lane & 15;
            int khalf = (lane >> 4) * 8;

            #pragma unroll
            for (int k16 = 0; k16 < 2; ++k16) {
                uint32_t koff = (uint32_t)(k16 * 16 + khalf) * 2u;
                uint32_t ah0r[4], ah1r[4], al0r[4], al1r[4];
                ldsm4(ah0r[0], ah0r[1], ah0r[2], ah0r[3], abase_h + (uint32_t)rrow * 80u + koff);
                ldsm4(ah1r[0], ah1r[1], ah1r[2], ah1r[3], abase_h + (uint32_t)(16 + rrow) * 80u + koff);
                ldsm4(al0r[0], al0r[1], al0r[2], al0r[3], abase_l + (uint32_t)rrow * 80u + koff);
                ldsm4(al1r[0], al1r[1], al1r[2], al1r[3], abase_l + (uint32_t)(16 + rrow) * 80u + koff);
                #pragma unroll
                for (int gg = 0; gg < 4; ++gg) {
                    uint32_t bh0, bh1, bh2, bh3, bl0, bl1, bl2, bl3;
                    ldsm4(bh0, bh1, bh2, bh3, bbase_h + (uint32_t)(gg * 16 + rrow) * 80u + koff);
                    ldsm4(bl0, bl1, bl2, bl3, bbase_l + (uint32_t)(gg * 16 + rrow) * 80u + koff);
                    mma16816(acc[2*gg  ][0], ah0r[0], ah0r[1], ah0r[2], ah0r[3], bh0, bh2);
                    mma16816(acc[2*gg+1][0], ah0r[0], ah0r[1], ah0r[2], ah0r[3], bh1, bh3);
                    mma16816(acc[2*gg  ][1], ah1r[0], ah1r[1], ah1r[2], ah1r[3], bh0, bh2);
                    mma16816(acc[2*gg+1][1], ah1r[0], ah1r[1], ah1r[2], ah1r[3], bh1, bh3);
                    mma16816(acc[2*gg  ][0], al0r[0], al0r[1], al0r[2], al0r[3], bh0, bh2);
                    mma16816(acc[2*gg+1][0], al0r[0], al0r[1], al0r[2], al0r[3], bh1, bh3);
                    mma16816(acc[2*gg  ][1], al1r[0], al1r[1], al1r[2], al1r[3], bh0, bh2);
                    mma16816(acc[2*gg+1][1], al1r[0], al1r[1], al1r[2], al1r[3], bh1, bh3);
                    mma16816(acc[2*gg  ][0], ah0r[0], ah0r[1], ah0r[2], ah0r[3], bl0, bl2);
                    mma16816(acc[2*gg+1][0], ah0r[0], ah0r[1], ah0r[2], ah0r[3], bl1, bl3);
                    mma16816(acc[2*gg  ][1], ah1r[0], ah1r[1], ah1r[2], ah1r[3], bl0, bl2);
                    mma16816(acc[2*gg+1][1], ah1r[0], ah1r[1], ah1r[2], ah1r[3], bl1, bl3);
                }
            }
            __syncthreads();            // all warps done reading buffers before reuse
        }

        // ---- queue B for chunk ch+1 (buffer (ch+1)&1 is now free) ----
        if (ch < NCH && ch + 1 < NCH) {
            const char* src = (const char*)(g_wb) + (size_t)(ch + 1) * BCHUNK;
            uint32_t dstb = sbase + SM_B + ((ch + 1) & 1) * BCHUNK;
            #pragma unroll
            for (int i = 0; i < 5; ++i)
                cp16(dstb + (tid + 512 * i) * 16, src + (size_t)(tid + 512 * i) * 16);
            CP_COMMIT();
        }
    }

    // ---- epilogue: direct stores from fragments ----
    {
        int mi = wid & 3;
        int nb = wid >> 2;
        int px0 = mi * 32;
        int re = px0 >> 6;              // image row of this warp's pixels (0 or 1)
        int h_o = 2 * hp + re;
        #pragma unroll
        for (int g = 0; g < 8; ++g) {
            int o0 = nb * 64 + g * 8 + 2 * (lane & 3);
            float b0 = __ldg(&bias[o0]);
            float b1 = __ldg(&bias[o0 + 1]);
            #pragma unroll
            for (int mt = 0; mt < 2; ++mt) {
                int px = px0 + mt * 16 + (lane >> 2);
                int wo = px & 63;
                float* p0 = out + (((size_t)b * COUT + o0) * 64 + h_o) * 64 + wo;
                p0[0]        = acc[g][mt][0] + b0;
                p0[4096]     = acc[g][mt][1] + b1;
                p0[8]        = acc[g][mt][2] + b0;
                p0[4096 + 8] = acc[g][mt][3] + b1;
            }
        }
    }
}

// ---------------- launch ----------------
extern "C" void kernel_launch(void* const* d_in, const int* in_sizes, int n_in,
                              void* d_out, int out_size) {
    const float* x      = (const float*)d_in[0];  // (4,256,64,64)
    const float* weight = (const float*)d_in[1];  // (256,256,3,3)
    const float* bias   = (const float*)d_in[2];  // (256,)
    const float* off_w  = (const float*)d_in[3];  // (18,256,3,3)
    const float* off_b  = (const float*)d_in[4];  // (18,)
    const float* mask_w = (const float*)d_in[5];  // (9,256,3,3)
    const float* mask_b = (const float*)d_in[6];  // (9,)
    float* out = (float*)d_out;                   // (4,256,64,64)

    cudaFuncSetAttribute(k_main, cudaFuncAttributeMaxDynamicSharedMemorySize, SMEM_TOTAL);

    prep_kernel<<<(COUT * KTOT + 255) / 256, 256>>>(weight, off_w, mask_w);
    k_offmask<<<BB * 64, 256>>>(x, off_b, mask_b);
    k_main<<<BB * 32, 512, SMEM_TOTAL>>>(x, bias, out);
}

// round 13
// speedup vs baseline: 3.7242x; 1.0629x over previous
#include <cuda_runtime.h>
#include <cuda_bf16.h>
#include <cstdint>

// Problem constants
#define BB   4
#define CIN  256
#define COUT 256
#define KTOT 2304
#define KC   32
#define NCH  72          // KTOT/KC
#define BROW 40          // padded smem row (bf16 elems): 80 B, 16B-aligned, ldmatrix conflict-free

// ---------------- device scratch (no allocations allowed) ----------------
__device__ float g_wofft[KTOT * 32];          // offset/mask conv weights [k][oc]
__device__ float g_offmask[BB*64*64*28];      // [b,h,w][28]
// Main weights, bf16 hi/lo split, padded rows, chunked: [ch][hi/lo][o][BROW]
__device__ __align__(16) __nv_bfloat16 g_wb[NCH * 2 * COUT * BROW];   // ~2.95 MB

// ---------------- PTX helpers (baseline ISA only: sm_80+ features) ----------------
__device__ __forceinline__ uint32_t smem_u32(const void* p) {
    uint32_t a;
    asm("{ .reg .u64 t; cvta.to.shared.u64 t, %1; cvt.u32.u64 %0, t; }" : "=r"(a) : "l"(p));
    return a;
}
__device__ __forceinline__ void cp16(uint32_t s, const void* g) {
    asm volatile("cp.async.cg.shared.global [%0], [%1], 16;" :: "r"(s), "l"(g));
}
#define CP_COMMIT() asm volatile("cp.async.commit_group;" ::: "memory")
#define CP_WAIT1()  asm volatile("cp.async.wait_group 1;" ::: "memory")
#define CP_WAIT0()  asm volatile("cp.async.wait_group 0;" ::: "memory")

__device__ __forceinline__ void ldsm4(uint32_t& r0, uint32_t& r1, uint32_t& r2, uint32_t& r3, uint32_t a) {
    asm volatile("ldmatrix.sync.aligned.m8n8.x4.shared.b16 {%0,%1,%2,%3}, [%4];"
                 : "=r"(r0), "=r"(r1), "=r"(r2), "=r"(r3) : "r"(a));
}
__device__ __forceinline__ void mma16816(float* d,
                                         uint32_t a0, uint32_t a1, uint32_t a2, uint32_t a3,
                                         uint32_t b0, uint32_t b1) {
    asm volatile("mma.sync.aligned.m16n8k16.row.col.f32.bf16.bf16.f32 "
                 "{%0,%1,%2,%3}, {%4,%5,%6,%7}, {%8,%9}, {%0,%1,%2,%3};"
                 : "+f"(d[0]), "+f"(d[1]), "+f"(d[2]), "+f"(d[3])
                 : "r"(a0), "r"(a1), "r"(a2), "r"(a3), "r"(b0), "r"(b1));
}

// SMEM layout (bytes, dynamic)
#define BCHUNK (2 * COUT * BROW * 2)           // 40960 B per chunk image (hi+lo)
#define SM_B     0                              // double buffered: 2 * 40960
#define SM_AH    (2 * BCHUNK)                   // 81920: As hi, 2 * (128*BROW*2 = 10240)
#define SM_AL    (SM_AH + 2 * 10240)            // 102400: As lo, 2 * 10240
#define SM_TADDR (SM_AL + 2 * 10240)            // 122880: u32[9*128*2] packed corner offsets
#define SM_TW    (SM_TADDR + 9216)              // 132096: float4[9*128] bilinear weights (mask folded)
#define SMEM_TOTAL (SM_TW + 18432)              // 150528

// ---------------- prep: weight split + conv-weight transpose ----------------
__global__ void prep_kernel(const float* __restrict__ w,
                            const float* __restrict__ off_w,
                            const float* __restrict__ mask_w) {
    int idx = blockIdx.x * blockDim.x + threadIdx.x;
    if (idx < COUT * KTOT) {
        int o = idx / KTOT;
        int k = idx - o * KTOT;          // k = c*9 + tap (matches w layout [o][c][3][3])
        float f = __ldg(&w[idx]);
        __nv_bfloat16 hi = __float2bfloat16(f);
        __nv_bfloat16 lo = __float2bfloat16(f - __bfloat162float(hi));
        int ch = k >> 5;
        int kk = k & 31;
        g_wb[((size_t)(ch * 2 + 0) * COUT + o) * BROW + kk] = hi;
        g_wb[((size_t)(ch * 2 + 1) * COUT + o) * BROW + kk] = lo;
    }
    if (idx < KTOT * 32) {
        int oc = idx & 31;
        int k  = idx >> 5;
        float v = 0.f;
        if (oc < 18)      v = __ldg(&off_w [(size_t)oc * KTOT + k]);
        else if (oc < 27) v = __ldg(&mask_w[(size_t)(oc - 18) * KTOT + k]);
        g_wofft[idx] = v;
    }
}

// ---------------- kernel 1: offset/mask conv (unchanged, FFMA) ----------------
#define CC1 16
__global__ __launch_bounds__(256, 2)
void k_offmask(const float* __restrict__ x,
               const float* __restrict__ off_b,
               const float* __restrict__ mask_b) {
    __shared__ float xs[CC1][3][66];
    __shared__ float ws[CC1 * 9 * 32];

    int bh = blockIdx.x;
    int b  = bh >> 6;
    int h  = bh & 63;
    int tid = threadIdx.x;
    int pp = tid & 31;
    int og = tid >> 5;

    const float* xb = x + (size_t)b * CIN * 4096;
    float acc[2][4] = {};

    for (int c0 = 0; c0 < CIN; c0 += CC1) {
        for (int e = tid; e < CC1 * 3 * 66; e += 256) {
            int c   = e / 198;
            int r   = e % 198;
            int row = r / 66;
            int col = r % 66;
            int y  = h - 1 + row;
            int xp = col - 1;
            float v = 0.f;
            if ((unsigned)y < 64u && (unsigned)xp < 64u)
                v = xb[(size_t)(c0 + c) * 4096 + y * 64 + xp];
            xs[c][row][col] = v;
        }
        const float* src = g_wofft + (size_t)c0 * 9 * 32;
        for (int e = tid; e < CC1 * 288; e += 256) ws[e] = src[e];
        __syncthreads();

        for (int c = 0; c < CC1; ++c) {
            #pragma unroll
            for (int t = 0; t < 9; ++t) {
                int ky = t / 3, kx = t % 3;
                float xv0 = xs[c][ky][pp + kx];
                float xv1 = xs[c][ky][pp + 32 + kx];
                const float* wr = &ws[(c * 9 + t) * 32 + og * 4];
                #pragma unroll
                for (int j = 0; j < 4; ++j) {
                    float wv = wr[j];
                    acc[0][j] = fmaf(xv0, wv, acc[0][j]);
                    acc[1][j] = fmaf(xv1, wv, acc[1][j]);
                }
            }
        }
        __syncthreads();
    }

    #pragma unroll
    for (int half = 0; half < 2; ++half) {
        int pix = pp + half * 32;
        float* dst = g_offmask + ((size_t)bh * 64 + pix) * 28;
        #pragma unroll
        for (int j = 0; j < 4; ++j) {
            int oc = og * 4 + j;
            if (oc < 18) {
                dst[oc] = acc[half][j] + __ldg(&off_b[oc]);
            } else if (oc < 27) {
                float z = acc[half][j] + __ldg(&mask_b[oc - 18]);
                dst[oc] = 1.f / (1.f + __expf(-z));
            }
        }
    }
}

// ---------------- kernel 2: deformable sample + bf16-split HMMA GEMM ----------------
// CTA: 128 px (2 rows) x 256 outs, 512 threads / 16 warps.
// Per-(pixel,tap) bilinear geometry (4 clamped corner offsets + 4 mask-folded
// weights, validity folded by zero-weights) precomputed ONCE into smem.
// Per-sample work in the k-loop: table LDS + 4 independent LDG + 4 FFMA + bf16 split.
__global__ __launch_bounds__(512, 1)
void k_main(const float* __restrict__ x,
            const float* __restrict__ bias,
            float* __restrict__ out) {
    extern __shared__ __align__(16) unsigned char smem[];
    uint32_t sbase = smem_u32(smem);
    uint32_t* taddr = (uint32_t*)(smem + SM_TADDR);   // [t*128+px]*2 + {0,1}
    float4*   twt   = (float4*)(smem + SM_TW);        // [t*128+px]

    int tid = threadIdx.x;
    int wid = tid >> 5;
    int lane = tid & 31;
    int bh = blockIdx.x;        // 0..127
    int b  = bh >> 5;
    int hp = bh & 31;           // image rows 2hp, 2hp+1

    // ---- precompute per-(px,tap) gather geometry ----
    for (int e = tid; e < 9 * 128; e += 512) {
        int t  = e >> 7;        // 0..8
        int px = e & 127;
        int r  = px >> 6, wi = px & 63;
        int h_img = 2 * hp + r;
        const float* om = g_offmask + (((size_t)(b * 64 + h_img)) * 64 + wi) * 28;
        float dy = om[2 * t], dx = om[2 * t + 1], m = om[18 + t];
        int kyy = t / 3, kxx = t - 3 * kyy;
        float py  = (float)(h_img - 1 + kyy) + dy;
        float pxf = (float)(wi - 1 + kxx) + dx;
        float y0f = floorf(py), x0f = floorf(pxf);
        int iy = (int)y0f, ix = (int)x0f;
        float fy = py - y0f, fx = pxf - x0f;
        bool y0v = (unsigned)iy       < 64u;
        bool y1v = (unsigned)(iy + 1) < 64u;
        bool x0v = (unsigned)ix       < 64u;
        bool x1v = (unsigned)(ix + 1) < 64u;
        int yc0 = min(max(iy, 0), 63),     yc1 = min(max(iy + 1, 0), 63);
        int xc0 = min(max(ix, 0), 63),     xc1 = min(max(ix + 1, 0), 63);
        float wy0 = 1.f - fy, wx0 = 1.f - fx;
        float4 w;
        w.x = (y0v && x0v) ? wy0 * wx0 * m : 0.f;
        w.y = (y0v && x1v) ? wy0 * fx  * m : 0.f;
        w.z = (y1v && x0v) ? fy  * wx0 * m : 0.f;
        w.w = (y1v && x1v) ? fy  * fx  * m : 0.f;
        taddr[e * 2 + 0] = (uint32_t)(yc0 * 64 + xc0) | ((uint32_t)(yc0 * 64 + xc1) << 16);
        taddr[e * 2 + 1] = (uint32_t)(yc1 * 64 + xc0) | ((uint32_t)(yc1 * 64 + xc1) << 16);
        twt[e] = w;
    }
    __syncthreads();

    const float* xb = x + (size_t)b * CIN * 4096;
    int p_img = tid & 127;      // pixel 0..127
    int ks = tid >> 7;          // 0..3

    float acc[8][2][4];
    #pragma unroll
    for (int g = 0; g < 8; ++g)
        #pragma unroll
        for (int mt = 0; mt < 2; ++mt)
            #pragma unroll
            for (int j = 0; j < 4; ++j) acc[g][mt][j] = 0.f;

    // prologue: stage B chunk 0 into buffer 0
    {
        const char* src = (const char*)(g_wb);
        uint32_t dstb = sbase + SM_B;
        #pragma unroll
        for (int i = 0; i < 5; ++i)
            cp16(dstb + (tid + 512 * i) * 16, src + (size_t)(tid + 512 * i) * 16);
    }
    CP_COMMIT();

    for (int ch = 0; ch <= NCH; ++ch) {
        // ---- stage A chunk ch into buffer ch&1 (plain smem stores) ----
        if (ch < NCH) {
            int p = ch & 1;
            int k0 = ch * KC;
            uint32_t aoff_h = SM_AH + p * 10240 + (uint32_t)p_img * 80u;
            uint32_t aoff_l = SM_AL + p * 10240 + (uint32_t)p_img * 80u;
            #pragma unroll
            for (int i = 0; i < 4; ++i) {
                int kp = ks + 4 * i;            // pair index 0..15
                uint32_t ph = 0, pl = 0;
                #pragma unroll
                for (int s2 = 0; s2 < 2; ++s2) {
                    int k = k0 + 2 * kp + s2;
                    unsigned c = (unsigned)k / 9u;
                    int t = k - 9 * (int)c;
                    int te = t * 128 + p_img;
                    uint32_t a01 = taddr[te * 2 + 0];
                    uint32_t a23 = taddr[te * 2 + 1];
                    float4 w = twt[te];
                    const float* xc = xb + ((size_t)c << 12);
                    float v00 = xc[a01 & 0xFFFFu];
                    float v01 = xc[a01 >> 16];
                    float v10 = xc[a23 & 0xFFFFu];
                    float v11 = xc[a23 >> 16];
                    float v = fmaf(w.w, v11, fmaf(w.z, v10, fmaf(w.y, v01, w.x * v00)));
                    __nv_bfloat16 hi = __float2bfloat16(v);
                    __nv_bfloat16 lo = __float2bfloat16(v - __bfloat162float(hi));
                    ph |= (uint32_t)__bfloat16_as_ushort(hi) << (16 * s2);
                    pl |= (uint32_t)__bfloat16_as_ushort(lo) << (16 * s2);
                }
                *(uint32_t*)(smem + aoff_h + kp * 4) = ph;
                *(uint32_t*)(smem + aoff_l + kp * 4) = pl;
            }
        }

        // ---- compute chunk ch-1 from buffer (ch-1)&1 ----
        if (ch > 0) {
            int cp = (ch - 1) & 1;
            if (ch == NCH) { CP_WAIT0(); } else { CP_WAIT1(); }   // B of chunk ch-1 resident
            __syncthreads();            // A stores of chunk ch-1 visible, B landed for all

            int mi = wid & 3;
            int nb = wid >> 2;
            int px0 = mi * 32;
            uint32_t abase_h = sbase + SM_AH + cp * 10240 + (uint32_t)px0 * 80u;
            uint32_t abase_l = sbase + SM_AL + cp * 10240 + (uint32_t)px0 * 80u;
            uint32_t bbase_h = sbase + SM_B + cp * BCHUNK + (uint32_t)(nb * 64) * 80u;
            uint32_t bbase_l = bbase_h + 20480u;
            int rrow = lane & 15;
            int khalf = (lane >> 4) * 8;

            #pragma unroll
            for (int k16 = 0; k16 < 2; ++k16) {
                uint32_t koff = (uint32_t)(k16 * 16 + khalf) * 2u;
                uint32_t ah0r[4], ah1r[4], al0r[4], al1r[4];
                ldsm4(ah0r[0], ah0r[1], ah0r[2], ah0r[3], abase_h + (uint32_t)rrow * 80u + koff);
                ldsm4(ah1r[0], ah1r[1], ah1r[2], ah1r[3], abase_h + (uint32_t)(16 + rrow) * 80u + koff);
                ldsm4(al0r[0], al0r[1], al0r[2], al0r[3], abase_l + (uint32_t)rrow * 80u + koff);
                ldsm4(al1r[0], al1r[1], al1r[2], al1r[3], abase_l + (uint32_t)(16 + rrow) * 80u + koff);
                #pragma unroll
                for (int gg = 0; gg < 4; ++gg) {
                    uint32_t bh0, bh1, bh2, bh3, bl0, bl1, bl2, bl3;
                    ldsm4(bh0, bh1, bh2, bh3, bbase_h + (uint32_t)(gg * 16 + rrow) * 80u + koff);
                    ldsm4(bl0, bl1, bl2, bl3, bbase_l + (uint32_t)(gg * 16 + rrow) * 80u + koff);
                    mma16816(acc[2*gg  ][0], ah0r[0], ah0r[1], ah0r[2], ah0r[3], bh0, bh2);
                    mma16816(acc[2*gg+1][0], ah0r[0], ah0r[1], ah0r[2], ah0r[3], bh1, bh3);
                    mma16816(acc[2*gg  ][1], ah1r[0], ah1r[1], ah1r[2], ah1r[3], bh0, bh2);
                    mma16816(acc[2*gg+1][1], ah1r[0], ah1r[1], ah1r[2], ah1r[3], bh1, bh3);
                    mma16816(acc[2*gg  ][0], al0r[0], al0r[1], al0r[2], al0r[3], bh0, bh2);
                    mma16816(acc[2*gg+1][0], al0r[0], al0r[1], al0r[2], al0r[3], bh1, bh3);
                    mma16816(acc[2*gg  ][1], al1r[0], al1r[1], al1r[2], al1r[3], bh0, bh2);
                    mma16816(acc[2*gg+1][1], al1r[0], al1r[1], al1r[2], al1r[3], bh1, bh3);
                    mma16816(acc[2*gg  ][0], ah0r[0], ah0r[1], ah0r[2], ah0r[3], bl0, bl2);
                    mma16816(acc[2*gg+1][0], ah0r[0], ah0r[1], ah0r[2], ah0r[3], bl1, bl3);
                    mma16816(acc[2*gg  ][1], ah1r[0], ah1r[1], ah1r[2], ah1r[3], bl0, bl2);
                    mma16816(acc[2*gg+1][1], ah1r[0], ah1r[1], ah1r[2], ah1r[3], bl1, bl3);
                }
            }
            __syncthreads();            // all warps done reading buffers before reuse
        }

        // ---- queue B for chunk ch+1 (buffer (ch+1)&1 is now free) ----
        if (ch < NCH && ch + 1 < NCH) {
            const char* src = (const char*)(g_wb) + (size_t)(ch + 1) * BCHUNK;
            uint32_t dstb = sbase + SM_B + ((ch + 1) & 1) * BCHUNK;
            #pragma unroll
            for (int i = 0; i < 5; ++i)
                cp16(dstb + (tid + 512 * i) * 16, src + (size_t)(tid + 512 * i) * 16);
            CP_COMMIT();
        }
    }

    // ---- epilogue: direct stores from fragments ----
    {
        int mi = wid & 3;
        int nb = wid >> 2;
        int px0 = mi * 32;
        int re = px0 >> 6;              // image row of this warp's pixels (0 or 1)
        int h_o = 2 * hp + re;
        #pragma unroll
        for (int g = 0; g < 8; ++g) {
            int o0 = nb * 64 + g * 8 + 2 * (lane & 3);
            float b0 = __ldg(&bias[o0]);
            float b1 = __ldg(&bias[o0 + 1]);
            #pragma unroll
            for (int mt = 0; mt < 2; ++mt) {
                int px = px0 + mt * 16 + (lane >> 2);
                int wo = px & 63;
                float* p0 = out + (((size_t)b * COUT + o0) * 64 + h_o) * 64 + wo;
                p0[0]        = acc[g][mt][0] + b0;
                p0[4096]     = acc[g][mt][1] + b1;
                p0[8]        = acc[g][mt][2] + b0;
                p0[4096 + 8] = acc[g][mt][3] + b1;
            }
        }
    }
}

// ---------------- launch ----------------
extern "C" void kernel_launch(void* const* d_in, const int* in_sizes, int n_in,
                              void* d_out, int out_size) {
    const float* x      = (const float*)d_in[0];  // (4,256,64,64)
    const float* weight = (const float*)d_in[1];  // (256,256,3,3)
    const float* bias   = (const float*)d_in[2];  // (256,)
    const float* off_w  = (const float*)d_in[3];  // (18,256,3,3)
    const float* off_b  = (const float*)d_in[4];  // (18,)
    const float* mask_w = (const float*)d_in[5];  // (9,256,3,3)
    const float* mask_b = (const float*)d_in[6];  // (9,)
    float* out = (float*)d_out;                   // (4,256,64,64)

    cudaFuncSetAttribute(k_main, cudaFuncAttributeMaxDynamicSharedMemorySize, SMEM_TOTAL);

    prep_kernel<<<(COUT * KTOT + 255) / 256, 256>>>(weight, off_w, mask_w);
    k_offmask<<<BB * 64, 256>>>(x, off_b, mask_b);
    k_main<<<BB * 32, 512, SMEM_TOTAL>>>(x, bias, out);
}